// round 2
// baseline (speedup 1.0000x reference)
#include <cuda_runtime.h>

// Problem constants
#define Nn   4096
#define Bb   4
#define Ff   32
#define NF   (Nn * Ff)        // 131072
#define BNF  (Bb * Nn * Ff)   // 524288
#define CC   256              // 2 sources * B * F columns in aggregation GEMM

// Scratch (no allocs allowed -> device globals)
__device__ float g_agg[Nn * CC];   // 4 MB: [N][256]  cols = src*128 + b*32 + f
__device__ float g_h1[BNF];        // 2 MB: h1 state between phases

// ---------------------------------------------------------------------------
// Packed f32x2 helpers (FFMA2 path: 2 FMAs per issue, 2x scalar FFMA rate)
// ---------------------------------------------------------------------------
__device__ __forceinline__ unsigned long long dup2(float s) {
    unsigned long long r;
    asm("mov.b64 %0, {%1, %1};" : "=l"(r) : "f"(s));
    return r;
}
__device__ __forceinline__ unsigned long long ffma2(unsigned long long a,
                                                    unsigned long long b,
                                                    unsigned long long c) {
    unsigned long long d;
    asm("fma.rn.f32x2 %0, %1, %2, %3;" : "=l"(d) : "l"(a), "l"(b), "l"(c));
    return d;
}

// ---------------------------------------------------------------------------
// Aggregation GEMM: out[N][256] = adj[N][N] @ S[N][256]
//   S[k][c]: c < 128 -> src0[b][k][f], c >= 128 -> src1[b][k][f], b=(c>>5)&3, f=c&31
// Tile: 128 rows x 64 cols, K-chunk 16, 256 threads, micro-tile 8x4
// Accumulators packed as float2 over row pairs -> fma.rn.f32x2
// ---------------------------------------------------------------------------
#define TM 128
#define TC 64
#define TK 16

__global__ __launch_bounds__(256)
void agg_kernel(const float* __restrict__ adj,
                const float* __restrict__ s0in,
                const float* __restrict__ s1,
                int s0_is_h1)
{
    __shared__ float As[TK][TM];   // adj tile, transposed: As[k][row]
    __shared__ float Ss[TK][TC];   // rhs tile

    const float* s0 = s0_is_h1 ? (const float*)g_h1 : s0in;

    const int tid = threadIdx.x;
    const int tx  = tid & 15;       // col group (4 cols each)
    const int ty  = tid >> 4;       // row group (8 rows each)
    const int m0  = blockIdx.x * TM;
    const int c0  = blockIdx.y * TC;

    // ---- S (rhs) load setup: one float4 per thread per chunk ----
    const int Ck   = c0 + (tid & 15) * 4;          // global col of this float4
    const float* sp = (Ck >= 128) ? s1 : s0;
    const int bb   = (Ck >> 5) & 3;
    const int ff   = Ck & 31;
    const int krow = tid >> 4;                     // 0..15
    const float* sbase = sp + bb * NF + krow * Ff + ff;

    // ---- A (adj) load setup: two float4 per thread per chunk ----
    const int arow0 = tid >> 2;                    // 0..63
    const int akq   = tid & 3;                     // which float4 along k
    const float* abase0 = adj + (long long)(m0 + arow0) * Nn + akq * 4;
    const float* abase1 = abase0 + 64LL * Nn;

    unsigned long long acc[4][4];
    #pragma unroll
    for (int p = 0; p < 4; p++)
        #pragma unroll
        for (int q = 0; q < 4; q++) acc[p][q] = 0ULL;

    // prefetch chunk 0
    float4 aR0 = *(const float4*)(abase0);
    float4 aR1 = *(const float4*)(abase1);
    float4 sR  = *(const float4*)(sbase);

    const int NCHUNK = Nn / TK;   // 256
    for (int kc = 0; kc < NCHUNK; kc++) {
        __syncthreads();
        // store prefetched regs to smem (A transposed)
        As[akq * 4 + 0][arow0]      = aR0.x;
        As[akq * 4 + 1][arow0]      = aR0.y;
        As[akq * 4 + 2][arow0]      = aR0.z;
        As[akq * 4 + 3][arow0]      = aR0.w;
        As[akq * 4 + 0][arow0 + 64] = aR1.x;
        As[akq * 4 + 1][arow0 + 64] = aR1.y;
        As[akq * 4 + 2][arow0 + 64] = aR1.z;
        As[akq * 4 + 3][arow0 + 64] = aR1.w;
        *(float4*)&Ss[krow][tx * 4] = sR;
        __syncthreads();

        // prefetch next chunk (hidden under compute)
        if (kc + 1 < NCHUNK) {
            const int k0n = (kc + 1) * TK;
            aR0 = *(const float4*)(abase0 + k0n);
            aR1 = *(const float4*)(abase1 + k0n);
            sR  = *(const float4*)(sbase + (long long)k0n * Ff);
        }

        #pragma unroll
        for (int kk = 0; kk < TK; kk++) {
            unsigned long long a0 = *(const unsigned long long*)&As[kk][ty * 8 + 0];
            unsigned long long a1 = *(const unsigned long long*)&As[kk][ty * 8 + 2];
            unsigned long long a2 = *(const unsigned long long*)&As[kk][ty * 8 + 4];
            unsigned long long a3 = *(const unsigned long long*)&As[kk][ty * 8 + 6];
            float4 s4 = *(const float4*)&Ss[kk][tx * 4];
            unsigned long long d0 = dup2(s4.x);
            unsigned long long d1 = dup2(s4.y);
            unsigned long long d2 = dup2(s4.z);
            unsigned long long d3 = dup2(s4.w);
            acc[0][0] = ffma2(a0, d0, acc[0][0]);
            acc[0][1] = ffma2(a0, d1, acc[0][1]);
            acc[0][2] = ffma2(a0, d2, acc[0][2]);
            acc[0][3] = ffma2(a0, d3, acc[0][3]);
            acc[1][0] = ffma2(a1, d0, acc[1][0]);
            acc[1][1] = ffma2(a1, d1, acc[1][1]);
            acc[1][2] = ffma2(a1, d2, acc[1][2]);
            acc[1][3] = ffma2(a1, d3, acc[1][3]);
            acc[2][0] = ffma2(a2, d0, acc[2][0]);
            acc[2][1] = ffma2(a2, d1, acc[2][1]);
            acc[2][2] = ffma2(a2, d2, acc[2][2]);
            acc[2][3] = ffma2(a2, d3, acc[2][3]);
            acc[3][0] = ffma2(a3, d0, acc[3][0]);
            acc[3][1] = ffma2(a3, d1, acc[3][1]);
            acc[3][2] = ffma2(a3, d2, acc[3][2]);
            acc[3][3] = ffma2(a3, d3, acc[3][3]);
        }
    }

    // epilogue: acc[p][q] holds (row r, row r+1) for col (c0+tx*4+q), r = m0+ty*8+2p
    #pragma unroll
    for (int p = 0; p < 4; p++) {
        float2 f0 = *(float2*)&acc[p][0];
        float2 f1 = *(float2*)&acc[p][1];
        float2 f2 = *(float2*)&acc[p][2];
        float2 f3 = *(float2*)&acc[p][3];
        const int r = m0 + ty * 8 + p * 2;
        *(float4*)&g_agg[(long long)r * CC + c0 + tx * 4] =
            make_float4(f0.x, f1.x, f2.x, f3.x);
        *(float4*)&g_agg[(long long)(r + 1) * CC + c0 + tx * 4] =
            make_float4(f0.y, f1.y, f2.y, f3.y);
    }
}

// ---------------------------------------------------------------------------
// Gate math helpers
// ---------------------------------------------------------------------------
__device__ __forceinline__ float sigm(float x) {
    return 1.0f / (1.0f + __expf(-x));
}

// ---------------------------------------------------------------------------
// Phase-1 gates: per (b,n): f,i,o,candidate from GLU(ax@W)+GLU(ah@W)
// c_new = f*c + i*tanh(cand); h1 = o*tanh(c_new)
// 2 threads per (b,n) (each handles 16 of the 32 feature outputs)
// W for 8 convs staged in dyn smem, swizzled so (l,r)=(j, j+32) columns are
// adjacent -> one LDS.64 per pair.
// ---------------------------------------------------------------------------
__global__ __launch_bounds__(256)
void gates1(const float* __restrict__ c_in,
            const float* __restrict__ W,
            const float* __restrict__ bias,
            float* __restrict__ c_out)
{
    extern __shared__ float dynsm[];
    float* Ws = dynsm;                 // 8*32*64 swizzled: [(g*32+k)*32 + j] -> float2(l,r)
    float* Bs = dynsm + 8 * 32 * 64;   // 8*64

    const int NW = 8 * 32 * 64;
    for (int i = threadIdx.x; i < NW; i += 256) {
        int j  = i & 63;
        int gk = i >> 6;
        int pos = (j < 32) ? (j * 2) : ((j - 32) * 2 + 1);
        Ws[gk * 64 + pos] = W[i];
    }
    for (int i = threadIdx.x; i < 8 * 64; i += 256) Bs[i] = bias[i];
    __syncthreads();

    const int gidx = blockIdx.x * 256 + threadIdx.x;  // 0..32767
    const int idx  = gidx >> 1;                       // (b,n) 0..16383
    const int jh   = gidx & 1;
    const int n    = idx & (Nn - 1);
    const int b    = idx >> 12;

    // load ax/ah rows into registers
    float ax[32], ah[32];
    const float* arow = g_agg + (long long)n * CC + b * Ff;
    #pragma unroll
    for (int k4 = 0; k4 < 8; k4++) {
        float4 vx = *(const float4*)(arow + k4 * 4);
        float4 vh = *(const float4*)(arow + 128 + k4 * 4);
        ax[k4 * 4 + 0] = vx.x; ax[k4 * 4 + 1] = vx.y;
        ax[k4 * 4 + 2] = vx.z; ax[k4 * 4 + 3] = vx.w;
        ah[k4 * 4 + 0] = vh.x; ah[k4 * 4 + 1] = vh.y;
        ah[k4 * 4 + 2] = vh.z; ah[k4 * 4 + 3] = vh.w;
    }

    const float* cptr  = c_in + (long long)idx * Ff;
    float* coptr = c_out + (long long)idx * Ff;
    float* h1ptr = g_h1 + (long long)idx * Ff;

    const float2* Wp = (const float2*)Ws;
    const int j0 = jh * 16;

    #pragma unroll 1
    for (int j = j0; j < j0 + 16; j++) {
        // accumulators: [gate g in {f,i,cand,o}] x {x_l, x_r, h_l, h_r}
        float s[16];
        #pragma unroll
        for (int g = 0; g < 4; g++) {
            s[g * 4 + 0] = Bs[(2 * g) * 64 + j];
            s[g * 4 + 1] = Bs[(2 * g) * 64 + j + 32];
            s[g * 4 + 2] = Bs[(2 * g + 1) * 64 + j];
            s[g * 4 + 3] = Bs[(2 * g + 1) * 64 + j + 32];
        }
        #pragma unroll
        for (int k = 0; k < 32; k++) {
            float axk = ax[k], ahk = ah[k];
            #pragma unroll
            for (int g = 0; g < 4; g++) {
                float2 wx = Wp[((2 * g) * 32 + k) * 32 + j];
                float2 wh = Wp[((2 * g + 1) * 32 + k) * 32 + j];
                s[g * 4 + 0] += axk * wx.x;
                s[g * 4 + 1] += axk * wx.y;
                s[g * 4 + 2] += ahk * wh.x;
                s[g * 4 + 3] += ahk * wh.y;
            }
        }
        float pre[4];
        #pragma unroll
        for (int g = 0; g < 4; g++)
            pre[g] = s[g * 4 + 0] * sigm(s[g * 4 + 1]) +
                     s[g * 4 + 2] * sigm(s[g * 4 + 3]);
        float fg = sigm(pre[0]);
        float ig = sigm(pre[1]);
        float og = sigm(pre[3]);
        float cn = fg * cptr[j] + ig * tanhf(pre[2]);
        coptr[j] = cn;
        h1ptr[j] = og * tanhf(cn);
    }
}

// ---------------------------------------------------------------------------
// Phase-2 gates: i2,g,o2 from GLU(ah1@W)+GLU(am@W); m_new = i2*m + (1-i2)*g;
// h_new = m_new * o2.  Uses W[8..13].
// ---------------------------------------------------------------------------
__global__ __launch_bounds__(256)
void gates2(const float* __restrict__ m_in,
            const float* __restrict__ W,
            const float* __restrict__ bias,
            float* __restrict__ h_out,
            float* __restrict__ m_out)
{
    extern __shared__ float dynsm[];
    float* Ws = dynsm;                 // 6*32*64 swizzled
    float* Bs = dynsm + 6 * 32 * 64;   // 6*64

    const float* Wsrc = W + 8 * 32 * 64;
    const float* Bsrc = bias + 8 * 64;
    const int NW = 6 * 32 * 64;
    for (int i = threadIdx.x; i < NW; i += 256) {
        int j  = i & 63;
        int gk = i >> 6;
        int pos = (j < 32) ? (j * 2) : ((j - 32) * 2 + 1);
        Ws[gk * 64 + pos] = Wsrc[i];
    }
    for (int i = threadIdx.x; i < 6 * 64; i += 256) Bs[i] = Bsrc[i];
    __syncthreads();

    const int gidx = blockIdx.x * 256 + threadIdx.x;
    const int idx  = gidx >> 1;
    const int jh   = gidx & 1;
    const int n    = idx & (Nn - 1);
    const int b    = idx >> 12;

    float a1[32], am[32];
    const float* arow = g_agg + (long long)n * CC + b * Ff;
    #pragma unroll
    for (int k4 = 0; k4 < 8; k4++) {
        float4 v1 = *(const float4*)(arow + k4 * 4);
        float4 vm = *(const float4*)(arow + 128 + k4 * 4);
        a1[k4 * 4 + 0] = v1.x; a1[k4 * 4 + 1] = v1.y;
        a1[k4 * 4 + 2] = v1.z; a1[k4 * 4 + 3] = v1.w;
        am[k4 * 4 + 0] = vm.x; am[k4 * 4 + 1] = vm.y;
        am[k4 * 4 + 2] = vm.z; am[k4 * 4 + 3] = vm.w;
    }

    const float* mptr = m_in + (long long)idx * Ff;
    float* hoptr = h_out + (long long)idx * Ff;
    float* moptr = m_out + (long long)idx * Ff;

    const float2* Wp = (const float2*)Ws;
    const int j0 = jh * 16;

    #pragma unroll 1
    for (int j = j0; j < j0 + 16; j++) {
        // accumulators: [gate g in {i2, g, o2}] x {h1_l, h1_r, m_l, m_r}
        float s[12];
        #pragma unroll
        for (int g = 0; g < 3; g++) {
            s[g * 4 + 0] = Bs[(2 * g) * 64 + j];
            s[g * 4 + 1] = Bs[(2 * g) * 64 + j + 32];
            s[g * 4 + 2] = Bs[(2 * g + 1) * 64 + j];
            s[g * 4 + 3] = Bs[(2 * g + 1) * 64 + j + 32];
        }
        #pragma unroll
        for (int k = 0; k < 32; k++) {
            float a1k = a1[k], amk = am[k];
            #pragma unroll
            for (int g = 0; g < 3; g++) {
                float2 wh = Wp[((2 * g) * 32 + k) * 32 + j];
                float2 wm = Wp[((2 * g + 1) * 32 + k) * 32 + j];
                s[g * 4 + 0] += a1k * wh.x;
                s[g * 4 + 1] += a1k * wh.y;
                s[g * 4 + 2] += amk * wm.x;
                s[g * 4 + 3] += amk * wm.y;
            }
        }
        float pre[3];
        #pragma unroll
        for (int g = 0; g < 3; g++)
            pre[g] = s[g * 4 + 0] * sigm(s[g * 4 + 1]) +
                     s[g * 4 + 2] * sigm(s[g * 4 + 3]);
        float i2 = sigm(pre[0]);
        float gg = sigm(pre[1]);
        float o2 = sigm(pre[2]);
        float mn = i2 * mptr[j] + (1.0f - i2) * gg;
        moptr[j] = mn;
        hoptr[j] = mn * o2;
    }
}

// ---------------------------------------------------------------------------
// Launch
// ---------------------------------------------------------------------------
extern "C" void kernel_launch(void* const* d_in, const int* in_sizes, int n_in,
                              void* d_out, int out_size) {
    const float* x    = (const float*)d_in[0];
    const float* h    = (const float*)d_in[1];
    const float* c    = (const float*)d_in[2];
    const float* m    = (const float*)d_in[3];
    const float* adj  = (const float*)d_in[4];
    const float* W    = (const float*)d_in[5];
    const float* bias = (const float*)d_in[6];

    float* out   = (float*)d_out;
    float* h_out = out;               // h_new
    float* c_out = out + BNF;         // c_new
    float* m_out = out + 2 * BNF;     // m_new

    const int smem1 = (8 * 32 * 64 + 8 * 64) * sizeof(float);   // ~66 KB
    const int smem2 = (6 * 32 * 64 + 6 * 64) * sizeof(float);   // ~50 KB
    cudaFuncSetAttribute(gates1, cudaFuncAttributeMaxDynamicSharedMemorySize, smem1);
    cudaFuncSetAttribute(gates2, cudaFuncAttributeMaxDynamicSharedMemorySize, smem2);

    dim3 agrid(Nn / TM, CC / TC);   // (32, 4)

    // Phase 1: aggregate x,h -> gates -> c_new, h1
    agg_kernel<<<agrid, 256>>>(adj, x, h, 0);
    gates1<<<128, 256, smem1>>>(c, W, bias, c_out);

    // Phase 2: aggregate h1,m -> gates -> m_new, h_new
    agg_kernel<<<agrid, 256>>>(adj, nullptr, m, 1);
    gates2<<<128, 256, smem2>>>(m, W, bias, h_out, m_out);
}

// round 7
// speedup vs baseline: 1.2804x; 1.2804x over previous
#include <cuda_runtime.h>
#include <cstdint>

// Problem constants
#define Nn   4096
#define Bb   4
#define Ff   32
#define NF   (Nn * Ff)        // 131072
#define BNF  (Bb * Nn * Ff)   // 524288
#define CC   256              // 2 sources * B * F columns in aggregation GEMM

// Scratch (no allocs allowed -> device globals)
__device__ float g_agg[Nn * CC];                         // 4 MB
__device__ float g_part[2 * Nn * CC];                    // 8 MB (k-split partials)
__device__ float g_h1[BNF];                              // 2 MB
__device__ __align__(16) float g_A32h[(long long)Nn * Nn];  // 64 MB adj tf32 hi
__device__ __align__(16) float g_A32l[(long long)Nn * Nn];  // 64 MB adj tf32 lo
__device__ __align__(16) float g_B32h[Nn * CC];          // 4 MB rhs tf32 hi, [k][j]
__device__ __align__(16) float g_B32l[Nn * CC];          // 4 MB rhs tf32 lo, [k][j]

// ---------------------------------------------------------------------------
// Helpers
// ---------------------------------------------------------------------------
__device__ __forceinline__ uint32_t smem_u32(const void* p) {
    uint32_t a;
    asm("{ .reg .u64 t; cvta.to.shared.u64 t, %1; cvt.u32.u64 %0, t; }"
        : "=r"(a) : "l"(p));
    return a;
}
__device__ __forceinline__ void cpa16(uint32_t s, const void* g) {
    asm volatile("cp.async.cg.shared.global [%0], [%1], 16;" :: "r"(s), "l"(g));
}
#define CP_COMMIT() asm volatile("cp.async.commit_group;" ::: "memory")

// non-trans ldmatrix: reads 16B/row segments; works for fp32 tiles viewed as b16
#define LDSM_X4(r0, r1, r2, r3, a) \
    asm volatile("ldmatrix.sync.aligned.m8n8.x4.shared.b16 {%0,%1,%2,%3}, [%4];" \
                 : "=r"(r0), "=r"(r1), "=r"(r2), "=r"(r3) : "r"(a))

__device__ __forceinline__ void mma1688(float* c, const uint32_t* a,
                                        uint32_t b0, uint32_t b1) {
    asm volatile(
        "mma.sync.aligned.m16n8k8.row.col.f32.tf32.tf32.f32 "
        "{%0,%1,%2,%3}, {%4,%5,%6,%7}, {%8,%9}, {%0,%1,%2,%3};"
        : "+f"(c[0]), "+f"(c[1]), "+f"(c[2]), "+f"(c[3])
        : "r"(a[0]), "r"(a[1]), "r"(a[2]), "r"(a[3]), "r"(b0), "r"(b1));
}

__device__ __forceinline__ float tf32r(float a) {
    float r;
    asm("cvt.rna.tf32.f32 %0, %1;" : "=f"(r) : "f"(a));
    return r;
}
// a = hi + lo + O(2^-23 a); both hi, lo are valid tf32 bit patterns
__device__ __forceinline__ void tsplit(float a, float& h, float& l) {
    h = tf32r(a);
    l = tf32r(a - h);
}

// ---------------------------------------------------------------------------
// conv_adj: adj fp32 -> (g_A32h, g_A32l) tf32-rounded fp32, row-major
// ---------------------------------------------------------------------------
__global__ __launch_bounds__(256)
void conv_adj(const float* __restrict__ adj) {
    long long i8 = ((long long)blockIdx.x * 256 + threadIdx.x) * 8;
    #pragma unroll
    for (int u = 0; u < 2; u++) {
        float4 v = *(const float4*)(adj + i8 + u * 4);
        float4 hv, lv;
        tsplit(v.x, hv.x, lv.x); tsplit(v.y, hv.y, lv.y);
        tsplit(v.z, hv.z, lv.z); tsplit(v.w, hv.w, lv.w);
        *(float4*)(g_A32h + i8 + u * 4) = hv;
        *(float4*)(g_A32l + i8 + u * 4) = lv;
    }
}

// ---------------------------------------------------------------------------
// conv_rhs: build B[k][j] = src[b][k][f] (j = src*128 + b*32 + f) tf32 hi/lo
// grid (128 k-chunks of 32, 8 = src*4 + b), 256 threads
// ---------------------------------------------------------------------------
__global__ __launch_bounds__(256)
void conv_rhs(const float* __restrict__ s0in, const float* __restrict__ s1,
              int s0_is_h1) {
    const int tid = threadIdx.x;
    const int f4  = tid & 7;          // float4 index along F
    const int kr  = tid >> 3;         // 0..31
    const int src = blockIdx.y >> 2;
    const int b   = blockIdx.y & 3;
    const int k   = blockIdx.x * 32 + kr;

    const float* s0 = s0_is_h1 ? (const float*)g_h1 : s0in;
    const float* sp = (src == 0) ? s0 : s1;

    float4 v = *(const float4*)(sp + b * NF + k * Ff + f4 * 4);
    float4 hv, lv;
    tsplit(v.x, hv.x, lv.x); tsplit(v.y, hv.y, lv.y);
    tsplit(v.z, hv.z, lv.z); tsplit(v.w, hv.w, lv.w);
    const int j = src * 128 + b * Ff + f4 * 4;
    *(float4*)(g_B32h + k * CC + j) = hv;
    *(float4*)(g_B32l + k * CC + j) = lv;
}

// ---------------------------------------------------------------------------
// agg_mma: g_part[ks][m][j] = sum_{k in ks range} adj[m][k] * S[k][j]
// tf32 3-pass split: Ah*Bh + Al*Bh + Ah*Bl (fp32 register accumulate).
// CTA tile 128(M) x 128(N), K-chunk 32, 2-stage cp.async.
// 8 warps as 4m x 2n -> warp tile 32x64. Grid (32 mt, 2 nt, 2 ks) = 128 CTAs.
// ---------------------------------------------------------------------------
#define AROWB 144                   // 32 fp32 = 128B data + 16B pad
#define BROWB 528                   // 128 fp32 = 512B + 16B pad (132 floats)
#define AH_O  0
#define AL_O  (128 * AROWB)         // 18432
#define BH_O  (2 * 128 * AROWB)     // 36864
#define BL_O  (BH_O + 32 * BROWB)   // 53760
#define STG_B (BL_O + 32 * BROWB)   // 70656
#define AGG_SMEM (2 * STG_B)        // 141312

__global__ __launch_bounds__(256, 1)
void agg_mma() {
    extern __shared__ __align__(16) char dsm[];
    const uint32_t sm0 = smem_u32(dsm);

    const int tid  = threadIdx.x;
    const int wid  = tid >> 5;
    const int lane = tid & 31;
    const int m0   = blockIdx.x * 128;
    const int n0   = blockIdx.y * 128;
    const int ksz  = blockIdx.z;
    const int kbase = ksz * 2048;

    const int wm = wid & 3;         // warp m (32 rows)
    const int wn = wid >> 2;        // warp n (64 cols)
    const int t  = lane & 3;        // thread-in-group (k for B)
    const int g  = lane >> 2;       // group (n for B, m for A/C)

    // A ldmatrix per-lane address (b16-view of fp32 rows)
    const int a_off = (wm * 32 + (lane & 15)) * AROWB + (lane >> 4) * 16;
    // B LDS base (float index within B tile)
    const int b_base = t * 132 + wn * 64 + g;

    float acc[2][8][4];
    #pragma unroll
    for (int mf = 0; mf < 2; mf++)
        #pragma unroll
        for (int nf = 0; nf < 8; nf++)
            #pragma unroll
            for (int q = 0; q < 4; q++) acc[mf][nf][q] = 0.0f;

    const int NKT = 2048 / 32;      // 64 chunks

    auto load_stage = [&](int st, int kc) {
        const uint32_t stg = sm0 + st * STG_B;
        const int k0 = kbase + kc * 32;
        // A: 128 rows x 8 segs (16B) per array
        #pragma unroll
        for (int i = 0; i < 4; i++) {
            int sid = tid + 256 * i;          // 0..1023
            int r = sid >> 3, s = sid & 7;
            long long goff = (long long)(m0 + r) * Nn + k0 + s * 4;
            uint32_t soff = r * AROWB + s * 16;
            cpa16(stg + AH_O + soff, g_A32h + goff);
            cpa16(stg + AL_O + soff, g_A32l + goff);
        }
        // B: 32 k-rows x 32 segs (16B) per array
        #pragma unroll
        for (int i = 0; i < 4; i++) {
            int sid = tid + 256 * i;          // 0..1023
            int r = sid >> 5, s = sid & 31;
            long long goff = (long long)(k0 + r) * CC + n0 + s * 4;
            uint32_t soff = r * BROWB + s * 16;
            cpa16(stg + BH_O + soff, g_B32h + goff);
            cpa16(stg + BL_O + soff, g_B32l + goff);
        }
    };

    load_stage(0, 0); CP_COMMIT();
    load_stage(1, 1); CP_COMMIT();

    for (int kc = 0; kc < NKT; kc++) {
        if (kc == NKT - 1) {
            asm volatile("cp.async.wait_group 0;" ::: "memory");
        } else {
            asm volatile("cp.async.wait_group 1;" ::: "memory");
        }
        __syncthreads();

        const int st = kc & 1;
        const uint32_t stg = sm0 + st * STG_B;
        const float* Bh = (const float*)(dsm + st * STG_B + BH_O);
        const float* Bl = (const float*)(dsm + st * STG_B + BL_O);

        #pragma unroll
        for (int k8 = 0; k8 < 4; k8++) {
            // A fragments (hi, lo) for both m16 frags
            uint32_t ah[2][4], al[2][4];
            const uint32_t aHb = stg + AH_O + a_off + k8 * 32;
            const uint32_t aLb = stg + AL_O + a_off + k8 * 32;
            LDSM_X4(ah[0][0], ah[0][1], ah[0][2], ah[0][3], aHb);
            LDSM_X4(ah[1][0], ah[1][1], ah[1][2], ah[1][3], aHb + 16 * AROWB);
            LDSM_X4(al[0][0], al[0][1], al[0][2], al[0][3], aLb);
            LDSM_X4(al[1][0], al[1][1], al[1][2], al[1][3], aLb + 16 * AROWB);

            // B fragments: b0 = B[k8*8+t][n], b1 = B[k8*8+t+4][n]
            const int kb = (k8 * 8) * 132 + b_base;
            uint32_t bh0[8], bh1[8], bl0[8], bl1[8];
            #pragma unroll
            for (int nf = 0; nf < 8; nf++) {
                bh0[nf] = __float_as_uint(Bh[kb + nf * 8]);
                bh1[nf] = __float_as_uint(Bh[kb + 528 + nf * 8]);
                bl0[nf] = __float_as_uint(Bl[kb + nf * 8]);
                bl1[nf] = __float_as_uint(Bl[kb + 528 + nf * 8]);
            }

            // pass 1: Ah * Bh
            #pragma unroll
            for (int mf = 0; mf < 2; mf++)
                #pragma unroll
                for (int nf = 0; nf < 8; nf++)
                    mma1688(acc[mf][nf], ah[mf], bh0[nf], bh1[nf]);
            // pass 2: Al * Bh
            #pragma unroll
            for (int mf = 0; mf < 2; mf++)
                #pragma unroll
                for (int nf = 0; nf < 8; nf++)
                    mma1688(acc[mf][nf], al[mf], bh0[nf], bh1[nf]);
            // pass 3: Ah * Bl
            #pragma unroll
            for (int mf = 0; mf < 2; mf++)
                #pragma unroll
                for (int nf = 0; nf < 8; nf++)
                    mma1688(acc[mf][nf], ah[mf], bl0[nf], bl1[nf]);
        }
        __syncthreads();

        if (kc + 2 < NKT) { load_stage(st, kc + 2); CP_COMMIT(); }
    }

    // Epilogue: write k-split partials
    float* outp = g_part + (long long)ksz * (Nn * CC);
    const int c2 = t * 2;
    #pragma unroll
    for (int mf = 0; mf < 2; mf++) {
        #pragma unroll
        for (int nf = 0; nf < 8; nf++) {
            const int row = m0 + wm * 32 + mf * 16 + g;
            const int col = n0 + wn * 64 + nf * 8 + c2;
            *(float2*)&outp[(long long)row * CC + col] =
                make_float2(acc[mf][nf][0], acc[mf][nf][1]);
            *(float2*)&outp[(long long)(row + 8) * CC + col] =
                make_float2(acc[mf][nf][2], acc[mf][nf][3]);
        }
    }
}

// ---------------------------------------------------------------------------
// reduce_agg: g_agg = part0 + part1
// ---------------------------------------------------------------------------
__global__ __launch_bounds__(256)
void reduce_agg() {
    const int i4 = blockIdx.x * 256 + threadIdx.x;   // 262144 float4s
    const float4* P = (const float4*)g_part;
    const int S = (Nn * CC) / 4;
    float4 a = P[i4], b = P[S + i4];
    ((float4*)g_agg)[i4] = make_float4(a.x + b.x, a.y + b.y, a.z + b.z, a.w + b.w);
}

// ---------------------------------------------------------------------------
// Gate math (unchanged from passing R2 lineage)
// ---------------------------------------------------------------------------
__device__ __forceinline__ float sigm(float x) {
    return 1.0f / (1.0f + __expf(-x));
}

__global__ __launch_bounds__(256)
void gates1(const float* __restrict__ c_in,
            const float* __restrict__ W,
            const float* __restrict__ bias,
            float* __restrict__ c_out)
{
    extern __shared__ float dynsm[];
    float* Ws = dynsm;                 // 8*32*64 swizzled pairs
    float* Bs = dynsm + 8 * 32 * 64;   // 8*64

    const int NW = 8 * 32 * 64;
    for (int i = threadIdx.x; i < NW; i += 256) {
        int j  = i & 63;
        int gk = i >> 6;
        int pos = (j < 32) ? (j * 2) : ((j - 32) * 2 + 1);
        Ws[gk * 64 + pos] = W[i];
    }
    for (int i = threadIdx.x; i < 8 * 64; i += 256) Bs[i] = bias[i];
    __syncthreads();

    const int gidx = blockIdx.x * 256 + threadIdx.x;  // 0..65535
    const int idx  = gidx >> 2;                       // (b,n)
    const int jh   = gidx & 3;
    const int n    = idx & (Nn - 1);
    const int b    = idx >> 12;

    float ax[32], ah[32];
    const float* arow = g_agg + (long long)n * CC + b * Ff;
    #pragma unroll
    for (int k4 = 0; k4 < 8; k4++) {
        float4 vx = *(const float4*)(arow + k4 * 4);
        float4 vh = *(const float4*)(arow + 128 + k4 * 4);
        ax[k4 * 4 + 0] = vx.x; ax[k4 * 4 + 1] = vx.y;
        ax[k4 * 4 + 2] = vx.z; ax[k4 * 4 + 3] = vx.w;
        ah[k4 * 4 + 0] = vh.x; ah[k4 * 4 + 1] = vh.y;
        ah[k4 * 4 + 2] = vh.z; ah[k4 * 4 + 3] = vh.w;
    }

    const float* cptr  = c_in + (long long)idx * Ff;
    float* coptr = c_out + (long long)idx * Ff;
    float* h1ptr = g_h1 + (long long)idx * Ff;

    const float2* Wp = (const float2*)Ws;
    const int j0 = jh * 8;

    #pragma unroll 1
    for (int j = j0; j < j0 + 8; j++) {
        float s[16];
        #pragma unroll
        for (int g = 0; g < 4; g++) {
            s[g * 4 + 0] = Bs[(2 * g) * 64 + j];
            s[g * 4 + 1] = Bs[(2 * g) * 64 + j + 32];
            s[g * 4 + 2] = Bs[(2 * g + 1) * 64 + j];
            s[g * 4 + 3] = Bs[(2 * g + 1) * 64 + j + 32];
        }
        #pragma unroll
        for (int k = 0; k < 32; k++) {
            float axk = ax[k], ahk = ah[k];
            #pragma unroll
            for (int g = 0; g < 4; g++) {
                float2 wx = Wp[((2 * g) * 32 + k) * 32 + j];
                float2 wh = Wp[((2 * g + 1) * 32 + k) * 32 + j];
                s[g * 4 + 0] += axk * wx.x;
                s[g * 4 + 1] += axk * wx.y;
                s[g * 4 + 2] += ahk * wh.x;
                s[g * 4 + 3] += ahk * wh.y;
            }
        }
        float pre[4];
        #pragma unroll
        for (int g = 0; g < 4; g++)
            pre[g] = s[g * 4 + 0] * sigm(s[g * 4 + 1]) +
                     s[g * 4 + 2] * sigm(s[g * 4 + 3]);
        float fg = sigm(pre[0]);
        float ig = sigm(pre[1]);
        float og = sigm(pre[3]);
        float cn = fg * cptr[j] + ig * tanhf(pre[2]);
        coptr[j] = cn;
        h1ptr[j] = og * tanhf(cn);
    }
}

__global__ __launch_bounds__(256)
void gates2(const float* __restrict__ m_in,
            const float* __restrict__ W,
            const float* __restrict__ bias,
            float* __restrict__ h_out,
            float* __restrict__ m_out)
{
    extern __shared__ float dynsm[];
    float* Ws = dynsm;                 // 6*32*64 swizzled
    float* Bs = dynsm + 6 * 32 * 64;   // 6*64

    const float* Wsrc = W + 8 * 32 * 64;
    const float* Bsrc = bias + 8 * 64;
    const int NW = 6 * 32 * 64;
    for (int i = threadIdx.x; i < NW; i += 256) {
        int j  = i & 63;
        int gk = i >> 6;
        int pos = (j < 32) ? (j * 2) : ((j - 32) * 2 + 1);
        Ws[gk * 64 + pos] = Wsrc[i];
    }
    for (int i = threadIdx.x; i < 6 * 64; i += 256) Bs[i] = Bsrc[i];
    __syncthreads();

    const int gidx = blockIdx.x * 256 + threadIdx.x;
    const int idx  = gidx >> 2;
    const int jh   = gidx & 3;
    const int n    = idx & (Nn - 1);
    const int b    = idx >> 12;

    float a1[32], am[32];
    const float* arow = g_agg + (long long)n * CC + b * Ff;
    #pragma unroll
    for (int k4 = 0; k4 < 8; k4++) {
        float4 v1 = *(const float4*)(arow + k4 * 4);
        float4 vm = *(const float4*)(arow + 128 + k4 * 4);
        a1[k4 * 4 + 0] = v1.x; a1[k4 * 4 + 1] = v1.y;
        a1[k4 * 4 + 2] = v1.z; a1[k4 * 4 + 3] = v1.w;
        am[k4 * 4 + 0] = vm.x; am[k4 * 4 + 1] = vm.y;
        am[k4 * 4 + 2] = vm.z; am[k4 * 4 + 3] = vm.w;
    }

    const float* mptr = m_in + (long long)idx * Ff;
    float* hoptr = h_out + (long long)idx * Ff;
    float* moptr = m_out + (long long)idx * Ff;

    const float2* Wp = (const float2*)Ws;
    const int j0 = jh * 8;

    #pragma unroll 1
    for (int j = j0; j < j0 + 8; j++) {
        float s[12];
        #pragma unroll
        for (int g = 0; g < 3; g++) {
            s[g * 4 + 0] = Bs[(2 * g) * 64 + j];
            s[g * 4 + 1] = Bs[(2 * g) * 64 + j + 32];
            s[g * 4 + 2] = Bs[(2 * g + 1) * 64 + j];
            s[g * 4 + 3] = Bs[(2 * g + 1) * 64 + j + 32];
        }
        #pragma unroll
        for (int k = 0; k < 32; k++) {
            float a1k = a1[k], amk = am[k];
            #pragma unroll
            for (int g = 0; g < 3; g++) {
                float2 wh = Wp[((2 * g) * 32 + k) * 32 + j];
                float2 wm = Wp[((2 * g + 1) * 32 + k) * 32 + j];
                s[g * 4 + 0] += a1k * wh.x;
                s[g * 4 + 1] += a1k * wh.y;
                s[g * 4 + 2] += amk * wm.x;
                s[g * 4 + 3] += amk * wm.y;
            }
        }
        float pre[3];
        #pragma unroll
        for (int g = 0; g < 3; g++)
            pre[g] = s[g * 4 + 0] * sigm(s[g * 4 + 1]) +
                     s[g * 4 + 2] * sigm(s[g * 4 + 3]);
        float i2 = sigm(pre[0]);
        float gg = sigm(pre[1]);
        float o2 = sigm(pre[2]);
        float mn = i2 * mptr[j] + (1.0f - i2) * gg;
        moptr[j] = mn;
        hoptr[j] = mn * o2;
    }
}

// ---------------------------------------------------------------------------
// Launch
// ---------------------------------------------------------------------------
extern "C" void kernel_launch(void* const* d_in, const int* in_sizes, int n_in,
                              void* d_out, int out_size) {
    const float* x    = (const float*)d_in[0];
    const float* h    = (const float*)d_in[1];
    const float* c    = (const float*)d_in[2];
    const float* m    = (const float*)d_in[3];
    const float* adj  = (const float*)d_in[4];
    const float* W    = (const float*)d_in[5];
    const float* bias = (const float*)d_in[6];

    float* out   = (float*)d_out;
    float* h_out = out;               // h_new
    float* c_out = out + BNF;         // c_new
    float* m_out = out + 2 * BNF;     // m_new

    const int smem1 = (8 * 32 * 64 + 8 * 64) * sizeof(float);
    const int smem2 = (6 * 32 * 64 + 6 * 64) * sizeof(float);
    cudaFuncSetAttribute(gates1, cudaFuncAttributeMaxDynamicSharedMemorySize, smem1);
    cudaFuncSetAttribute(gates2, cudaFuncAttributeMaxDynamicSharedMemorySize, smem2);
    cudaFuncSetAttribute(agg_mma, cudaFuncAttributeMaxDynamicSharedMemorySize, AGG_SMEM);

    // Split adj into tf32 hi/lo (once per call)
    conv_adj<<<8192, 256>>>(adj);

    dim3 agrid(32, 2, 2);

    // Phase 1
    conv_rhs<<<dim3(128, 8), 256>>>(x, h, 0);
    agg_mma<<<agrid, 256, AGG_SMEM>>>();
    reduce_agg<<<1024, 256>>>();
    gates1<<<256, 256, smem1>>>(c, W, bias, c_out);

    // Phase 2
    conv_rhs<<<dim3(128, 8), 256>>>(nullptr, m, 1);
    agg_mma<<<agrid, 256, AGG_SMEM>>>();
    reduce_agg<<<1024, 256>>>();
    gates2<<<256, 256, smem2>>>(m, W, bias, h_out, m_out);
}

// round 10
// speedup vs baseline: 1.3808x; 1.0784x over previous
#include <cuda_runtime.h>
#include <cstdint>

// Problem constants
#define Nn   4096
#define Bb   4
#define Ff   32
#define NF   (Nn * Ff)        // 131072
#define BNF  (Bb * Nn * Ff)   // 524288
#define CC   256              // 2 sources * B * F columns in aggregation GEMM

// Scratch (no allocs allowed -> device globals)
__device__ float g_agg[Nn * CC];                       // 4 MB
__device__ float g_part[2 * Nn * CC];                  // 8 MB (k-split partials)
__device__ float g_h1[BNF];                            // 2 MB
__device__ __align__(16) float g_Bt[CC * Nn];          // 4 MB rhs fp32, [j][k]

// ---------------------------------------------------------------------------
// Helpers
// ---------------------------------------------------------------------------
__device__ __forceinline__ uint32_t smem_u32(const void* p) {
    uint32_t a;
    asm("{ .reg .u64 t; cvta.to.shared.u64 t, %1; cvt.u32.u64 %0, t; }"
        : "=r"(a) : "l"(p));
    return a;
}
__device__ __forceinline__ void cpa16(uint32_t s, const void* g) {
    asm volatile("cp.async.cg.shared.global [%0], [%1], 16;" :: "r"(s), "l"(g));
}
#define CP_COMMIT() asm volatile("cp.async.commit_group;" ::: "memory")

#define LDSM_X4(r0, r1, r2, r3, a) \
    asm volatile("ldmatrix.sync.aligned.m8n8.x4.shared.b16 {%0,%1,%2,%3}, [%4];" \
                 : "=r"(r0), "=r"(r1), "=r"(r2), "=r"(r3) : "r"(a))

__device__ __forceinline__ void mma1688(float* c, const uint32_t* a,
                                        uint32_t b0, uint32_t b1) {
    asm volatile(
        "mma.sync.aligned.m16n8k8.row.col.f32.tf32.tf32.f32 "
        "{%0,%1,%2,%3}, {%4,%5,%6,%7}, {%8,%9}, {%0,%1,%2,%3};"
        : "+f"(c[0]), "+f"(c[1]), "+f"(c[2]), "+f"(c[3])
        : "r"(a[0]), "r"(a[1]), "r"(a[2]), "r"(a[3]), "r"(b0), "r"(b1));
}

// Exact register split: hi = trunc-to-tf32(a) (mask is a valid tf32 pattern),
// lo = a - hi exact in fp32, then masked to tf32. hi+lo = a up to ~2^-24 a.
__device__ __forceinline__ void tsplit2(uint32_t r, uint32_t& h, uint32_t& l) {
    h = r & 0xFFFFE000u;
    float lf = __uint_as_float(r) - __uint_as_float(h);
    l = __float_as_uint(lf) & 0xFFFFE000u;
}

// ---------------------------------------------------------------------------
// conv_rhs: build Bt[j][k] = src[b][k][f] (j = src*128 + b*32 + f), raw fp32
// grid (64 k-chunks of 64, 8 = src*4 + b), 256 threads; smem transpose
// ---------------------------------------------------------------------------
__global__ __launch_bounds__(256)
void conv_rhs(const float* __restrict__ s0in, const float* __restrict__ s1,
              int s0_is_h1) {
    __shared__ float t[64][33];
    const int tid = threadIdx.x;
    const int src = blockIdx.y >> 2;
    const int b   = blockIdx.y & 3;
    const int k0  = blockIdx.x * 64;

    const float* s0 = s0_is_h1 ? (const float*)g_h1 : s0in;
    const float* sp = (src == 0) ? s0 : s1;
    const float* base = sp + b * NF + k0 * Ff;

    #pragma unroll
    for (int i = 0; i < 2; i++) {
        int fi = tid + 256 * i;            // 0..511 float4s
        int row = fi >> 3, quad = fi & 7;
        float4 v = *(const float4*)(base + row * Ff + quad * 4);
        t[row][quad * 4 + 0] = v.x; t[row][quad * 4 + 1] = v.y;
        t[row][quad * 4 + 2] = v.z; t[row][quad * 4 + 3] = v.w;
    }
    __syncthreads();

    const int j0 = src * 128 + b * Ff;
    #pragma unroll
    for (int i = 0; i < 2; i++) {
        int oi = tid + 256 * i;            // 0..511
        int f  = oi >> 4;                  // 0..31
        int kq = oi & 15;                  // float4 along k
        float4 v = make_float4(t[kq * 4 + 0][f], t[kq * 4 + 1][f],
                               t[kq * 4 + 2][f], t[kq * 4 + 3][f]);
        *(float4*)(g_Bt + (long long)(j0 + f) * Nn + k0 + kq * 4) = v;
    }
}

// ---------------------------------------------------------------------------
// agg_mma: g_part[ks][m][j] = sum_{k in ks range} adj[m][k] * S[k][j]
// tf32 3-pass register-split GEMM. A staged raw fp32 from adj, B raw fp32 from
// g_Bt (both [row][k], 32-float rows). All fragments via ldmatrix; hi/lo split
// in registers. CTA tile 128(M) x 128(N), K-chunk 32, 2-stage cp.async.
// 8 warps 4m x 2n -> warp tile 32x64. Grid (32 mt, 2 nt, 2 ks) = 128 CTAs.
// ---------------------------------------------------------------------------
#define AROWB 144                   // 32 fp32 = 128B + 16B pad
#define A_O   0
#define B_O   (128 * AROWB)         // 18432
#define STG_B (2 * 128 * AROWB)     // 36864
#define AGG_SMEM (2 * STG_B)        // 73728

__global__ __launch_bounds__(256, 1)
void agg_mma(const float* __restrict__ Araw) {
    extern __shared__ __align__(16) char dsm[];
    const uint32_t sm0 = smem_u32(dsm);

    const int tid  = threadIdx.x;
    const int wid  = tid >> 5;
    const int lane = tid & 31;
    const int m0   = blockIdx.x * 128;
    const int n0   = blockIdx.y * 128;
    const int ksz  = blockIdx.z;
    const int kbase = ksz * 2048;

    const int wm = wid & 3;         // warp m (32 rows)
    const int wn = wid >> 2;        // warp n (64 cols)
    const int t  = lane & 3;
    const int g  = lane >> 2;

    // ldmatrix per-lane addresses (16-row x 2-seg pattern, fp32 rows as b16)
    const int a_off = (wm * 32 + (lane & 15)) * AROWB + (lane >> 4) * 16;
    const int b_off = (wn * 64 + (lane & 15)) * AROWB + (lane >> 4) * 16;

    float acc[2][8][4];
    #pragma unroll
    for (int mf = 0; mf < 2; mf++)
        #pragma unroll
        for (int nf = 0; nf < 8; nf++)
            #pragma unroll
            for (int q = 0; q < 4; q++) acc[mf][nf][q] = 0.0f;

    const int NKT = 2048 / 32;      // 64 chunks

    auto load_stage = [&](int st, int kc) {
        const uint32_t stg = sm0 + st * STG_B;
        const int k0 = kbase + kc * 32;
        #pragma unroll
        for (int i = 0; i < 4; i++) {
            int sid = tid + 256 * i;          // 0..1023
            int r = sid >> 3, s = sid & 7;
            uint32_t soff = r * AROWB + s * 16;
            cpa16(stg + A_O + soff, Araw + (long long)(m0 + r) * Nn + k0 + s * 4);
            cpa16(stg + B_O + soff, g_Bt + (long long)(n0 + r) * Nn + k0 + s * 4);
        }
    };

    load_stage(0, 0); CP_COMMIT();
    load_stage(1, 1); CP_COMMIT();

    for (int kc = 0; kc < NKT; kc++) {
        if (kc == NKT - 1) {
            asm volatile("cp.async.wait_group 0;" ::: "memory");
        } else {
            asm volatile("cp.async.wait_group 1;" ::: "memory");
        }
        __syncthreads();

        const int st = kc & 1;
        const uint32_t stg = sm0 + st * STG_B;

        #pragma unroll
        for (int k8 = 0; k8 < 4; k8++) {
            const uint32_t ko = k8 * 32;   // 8 floats = 32B

            // ---- A fragments: raw, then split in registers ----
            uint32_t ar0[4], ar1[4];
            LDSM_X4(ar0[0], ar0[1], ar0[2], ar0[3], stg + A_O + a_off + ko);
            LDSM_X4(ar1[0], ar1[1], ar1[2], ar1[3],
                    stg + A_O + a_off + ko + 16 * AROWB);
            uint32_t ah[2][4], al[2][4];
            #pragma unroll
            for (int q = 0; q < 4; q++) {
                tsplit2(ar0[q], ah[0][q], al[0][q]);
                tsplit2(ar1[q], ah[1][q], al[1][q]);
            }

            // ---- B fragments per 16-n group ----
            #pragma unroll
            for (int nbi = 0; nbi < 4; nbi++) {
                uint32_t br[4];
                LDSM_X4(br[0], br[1], br[2], br[3],
                        stg + B_O + b_off + nbi * 16 * AROWB + ko);
                uint32_t bh[4], bl[4];
                #pragma unroll
                for (int q = 0; q < 4; q++) tsplit2(br[q], bh[q], bl[q]);

                const int nf0 = nbi * 2;
                // pass 1: Ah*Bh
                mma1688(acc[0][nf0 + 0], ah[0], bh[0], bh[2]);
                mma1688(acc[0][nf0 + 1], ah[0], bh[1], bh[3]);
                mma1688(acc[1][nf0 + 0], ah[1], bh[0], bh[2]);
                mma1688(acc[1][nf0 + 1], ah[1], bh[1], bh[3]);
                // pass 2: Al*Bh
                mma1688(acc[0][nf0 + 0], al[0], bh[0], bh[2]);
                mma1688(acc[0][nf0 + 1], al[0], bh[1], bh[3]);
                mma1688(acc[1][nf0 + 0], al[1], bh[0], bh[2]);
                mma1688(acc[1][nf0 + 1], al[1], bh[1], bh[3]);
                // pass 3: Ah*Bl
                mma1688(acc[0][nf0 + 0], ah[0], bl[0], bl[2]);
                mma1688(acc[0][nf0 + 1], ah[0], bl[1], bl[3]);
                mma1688(acc[1][nf0 + 0], ah[1], bl[0], bl[2]);
                mma1688(acc[1][nf0 + 1], ah[1], bl[1], bl[3]);
            }
        }
        __syncthreads();

        if (kc + 2 < NKT) { load_stage(st, kc + 2); CP_COMMIT(); }
    }

    // Epilogue: write k-split partials
    float* outp = g_part + (long long)ksz * (Nn * CC);
    const int c2 = t * 2;
    #pragma unroll
    for (int mf = 0; mf < 2; mf++) {
        #pragma unroll
        for (int nf = 0; nf < 8; nf++) {
            const int row = m0 + wm * 32 + mf * 16 + g;
            const int col = n0 + wn * 64 + nf * 8 + c2;
            *(float2*)&outp[(long long)row * CC + col] =
                make_float2(acc[mf][nf][0], acc[mf][nf][1]);
            *(float2*)&outp[(long long)(row + 8) * CC + col] =
                make_float2(acc[mf][nf][2], acc[mf][nf][3]);
        }
    }
}

// ---------------------------------------------------------------------------
// reduce_agg: g_agg = part0 + part1
// ---------------------------------------------------------------------------
__global__ __launch_bounds__(256)
void reduce_agg() {
    const int i4 = blockIdx.x * 256 + threadIdx.x;   // 262144 float4s
    const float4* P = (const float4*)g_part;
    const int S = (Nn * CC) / 4;
    float4 a = P[i4], b = P[S + i4];
    ((float4*)g_agg)[i4] = make_float4(a.x + b.x, a.y + b.y, a.z + b.z, a.w + b.w);
}

// ---------------------------------------------------------------------------
// Gate math (8 threads per (b,n) row, 4 j each)
// ---------------------------------------------------------------------------
__device__ __forceinline__ float sigm(float x) {
    return 1.0f / (1.0f + __expf(-x));
}

__global__ __launch_bounds__(256)
void gates1(const float* __restrict__ c_in,
            const float* __restrict__ W,
            const float* __restrict__ bias,
            float* __restrict__ c_out)
{
    extern __shared__ float dynsm[];
    float* Ws = dynsm;                 // 8*32*64 swizzled pairs
    float* Bs = dynsm + 8 * 32 * 64;   // 8*64

    const int NW = 8 * 32 * 64;
    for (int i = threadIdx.x; i < NW; i += 256) {
        int j  = i & 63;
        int gk = i >> 6;
        int pos = (j < 32) ? (j * 2) : ((j - 32) * 2 + 1);
        Ws[gk * 64 + pos] = W[i];
    }
    for (int i = threadIdx.x; i < 8 * 64; i += 256) Bs[i] = bias[i];
    __syncthreads();

    const int gidx = blockIdx.x * 256 + threadIdx.x;  // 0..131071
    const int idx  = gidx >> 3;                       // (b,n)
    const int jh   = gidx & 7;
    const int n    = idx & (Nn - 1);
    const int b    = idx >> 12;

    float ax[32], ah[32];
    const float* arow = g_agg + (long long)n * CC + b * Ff;
    #pragma unroll
    for (int k4 = 0; k4 < 8; k4++) {
        float4 vx = *(const float4*)(arow + k4 * 4);
        float4 vh = *(const float4*)(arow + 128 + k4 * 4);
        ax[k4 * 4 + 0] = vx.x; ax[k4 * 4 + 1] = vx.y;
        ax[k4 * 4 + 2] = vx.z; ax[k4 * 4 + 3] = vx.w;
        ah[k4 * 4 + 0] = vh.x; ah[k4 * 4 + 1] = vh.y;
        ah[k4 * 4 + 2] = vh.z; ah[k4 * 4 + 3] = vh.w;
    }

    const float* cptr  = c_in + (long long)idx * Ff;
    float* coptr = c_out + (long long)idx * Ff;
    float* h1ptr = g_h1 + (long long)idx * Ff;

    const float2* Wp = (const float2*)Ws;
    const int j0 = jh * 4;

    #pragma unroll 1
    for (int j = j0; j < j0 + 4; j++) {
        float s[16];
        #pragma unroll
        for (int g = 0; g < 4; g++) {
            s[g * 4 + 0] = Bs[(2 * g) * 64 + j];
            s[g * 4 + 1] = Bs[(2 * g) * 64 + j + 32];
            s[g * 4 + 2] = Bs[(2 * g + 1) * 64 + j];
            s[g * 4 + 3] = Bs[(2 * g + 1) * 64 + j + 32];
        }
        #pragma unroll
        for (int k = 0; k < 32; k++) {
            float axk = ax[k], ahk = ah[k];
            #pragma unroll
            for (int g = 0; g < 4; g++) {
                float2 wx = Wp[((2 * g) * 32 + k) * 32 + j];
                float2 wh = Wp[((2 * g + 1) * 32 + k) * 32 + j];
                s[g * 4 + 0] += axk * wx.x;
                s[g * 4 + 1] += axk * wx.y;
                s[g * 4 + 2] += ahk * wh.x;
                s[g * 4 + 3] += ahk * wh.y;
            }
        }
        float pre[4];
        #pragma unroll
        for (int g = 0; g < 4; g++)
            pre[g] = s[g * 4 + 0] * sigm(s[g * 4 + 1]) +
                     s[g * 4 + 2] * sigm(s[g * 4 + 3]);
        float fg = sigm(pre[0]);
        float ig = sigm(pre[1]);
        float og = sigm(pre[3]);
        float cn = fg * cptr[j] + ig * tanhf(pre[2]);
        coptr[j] = cn;
        h1ptr[j] = og * tanhf(cn);
    }
}

__global__ __launch_bounds__(256)
void gates2(const float* __restrict__ m_in,
            const float* __restrict__ W,
            const float* __restrict__ bias,
            float* __restrict__ h_out,
            float* __restrict__ m_out)
{
    extern __shared__ float dynsm[];
    float* Ws = dynsm;                 // 6*32*64 swizzled
    float* Bs = dynsm + 6 * 32 * 64;   // 6*64

    const float* Wsrc = W + 8 * 32 * 64;
    const float* Bsrc = bias + 8 * 64;
    const int NW = 6 * 32 * 64;
    for (int i = threadIdx.x; i < NW; i += 256) {
        int j  = i & 63;
        int gk = i >> 6;
        int pos = (j < 32) ? (j * 2) : ((j - 32) * 2 + 1);
        Ws[gk * 64 + pos] = Wsrc[i];
    }
    for (int i = threadIdx.x; i < 6 * 64; i += 256) Bs[i] = Bsrc[i];
    __syncthreads();

    const int gidx = blockIdx.x * 256 + threadIdx.x;
    const int idx  = gidx >> 3;
    const int jh   = gidx & 7;
    const int n    = idx & (Nn - 1);
    const int b    = idx >> 12;

    float a1[32], am[32];
    const float* arow = g_agg + (long long)n * CC + b * Ff;
    #pragma unroll
    for (int k4 = 0; k4 < 8; k4++) {
        float4 v1 = *(const float4*)(arow + k4 * 4);
        float4 vm = *(const float4*)(arow + 128 + k4 * 4);
        a1[k4 * 4 + 0] = v1.x; a1[k4 * 4 + 1] = v1.y;
        a1[k4 * 4 + 2] = v1.z; a1[k4 * 4 + 3] = v1.w;
        am[k4 * 4 + 0] = vm.x; am[k4 * 4 + 1] = vm.y;
        am[k4 * 4 + 2] = vm.z; am[k4 * 4 + 3] = vm.w;
    }

    const float* mptr = m_in + (long long)idx * Ff;
    float* hoptr = h_out + (long long)idx * Ff;
    float* moptr = m_out + (long long)idx * Ff;

    const float2* Wp = (const float2*)Ws;
    const int j0 = jh * 4;

    #pragma unroll 1
    for (int j = j0; j < j0 + 4; j++) {
        float s[12];
        #pragma unroll
        for (int g = 0; g < 3; g++) {
            s[g * 4 + 0] = Bs[(2 * g) * 64 + j];
            s[g * 4 + 1] = Bs[(2 * g) * 64 + j + 32];
            s[g * 4 + 2] = Bs[(2 * g + 1) * 64 + j];
            s[g * 4 + 3] = Bs[(2 * g + 1) * 64 + j + 32];
        }
        #pragma unroll
        for (int k = 0; k < 32; k++) {
            float a1k = a1[k], amk = am[k];
            #pragma unroll
            for (int g = 0; g < 3; g++) {
                float2 wh = Wp[((2 * g) * 32 + k) * 32 + j];
                float2 wm = Wp[((2 * g + 1) * 32 + k) * 32 + j];
                s[g * 4 + 0] += a1k * wh.x;
                s[g * 4 + 1] += a1k * wh.y;
                s[g * 4 + 2] += amk * wm.x;
                s[g * 4 + 3] += amk * wm.y;
            }
        }
        float pre[3];
        #pragma unroll
        for (int g = 0; g < 3; g++)
            pre[g] = s[g * 4 + 0] * sigm(s[g * 4 + 1]) +
                     s[g * 4 + 2] * sigm(s[g * 4 + 3]);
        float i2 = sigm(pre[0]);
        float gg = sigm(pre[1]);
        float o2 = sigm(pre[2]);
        float mn = i2 * mptr[j] + (1.0f - i2) * gg;
        moptr[j] = mn;
        hoptr[j] = mn * o2;
    }
}

// ---------------------------------------------------------------------------
// Launch
// ---------------------------------------------------------------------------
extern "C" void kernel_launch(void* const* d_in, const int* in_sizes, int n_in,
                              void* d_out, int out_size) {
    const float* x    = (const float*)d_in[0];
    const float* h    = (const float*)d_in[1];
    const float* c    = (const float*)d_in[2];
    const float* m    = (const float*)d_in[3];
    const float* adj  = (const float*)d_in[4];
    const float* W    = (const float*)d_in[5];
    const float* bias = (const float*)d_in[6];

    float* out   = (float*)d_out;
    float* h_out = out;               // h_new
    float* c_out = out + BNF;         // c_new
    float* m_out = out + 2 * BNF;     // m_new

    const int smem1 = (8 * 32 * 64 + 8 * 64) * sizeof(float);
    const int smem2 = (6 * 32 * 64 + 6 * 64) * sizeof(float);
    cudaFuncSetAttribute(gates1, cudaFuncAttributeMaxDynamicSharedMemorySize, smem1);
    cudaFuncSetAttribute(gates2, cudaFuncAttributeMaxDynamicSharedMemorySize, smem2);
    cudaFuncSetAttribute(agg_mma, cudaFuncAttributeMaxDynamicSharedMemorySize, AGG_SMEM);

    dim3 agrid(32, 2, 2);

    // Phase 1
    conv_rhs<<<dim3(64, 8), 256>>>(x, h, 0);
    agg_mma<<<agrid, 256, AGG_SMEM>>>(adj);
    reduce_agg<<<1024, 256>>>();
    gates1<<<512, 256, smem1>>>(c, W, bias, c_out);

    // Phase 2
    conv_rhs<<<dim3(64, 8), 256>>>(nullptr, m, 1);
    agg_mma<<<agrid, 256, AGG_SMEM>>>(adj);
    reduce_agg<<<1024, 256>>>();
    gates2<<<512, 256, smem2>>>(m, W, bias, h_out, m_out);
}

// round 12
// speedup vs baseline: 1.6166x; 1.1708x over previous
#include <cuda_runtime.h>
#include <cstdint>

// Problem constants
#define Nn   4096
#define Bb   4
#define Ff   32
#define NF   (Nn * Ff)        // 131072
#define BNF  (Bb * Nn * Ff)   // 524288
#define CC   256              // 2 sources * B * F columns in aggregation GEMM

// Scratch (no allocs allowed -> device globals)
__device__ float g_agg[Nn * CC];                       // 4 MB
__device__ float g_part[2 * Nn * CC];                  // 8 MB (k-split partials)
__device__ float g_h1[BNF];                            // 2 MB
__device__ __align__(16) float g_Bt[CC * Nn];          // 4 MB rhs fp32, [j][k]
__device__ __align__(16) float g_Wt[14 * 64 * 32];     // W transposed: [conv][j][k]

// ---------------------------------------------------------------------------
// Helpers
// ---------------------------------------------------------------------------
__device__ __forceinline__ uint32_t smem_u32(const void* p) {
    uint32_t a;
    asm("{ .reg .u64 t; cvta.to.shared.u64 t, %1; cvt.u32.u64 %0, t; }"
        : "=r"(a) : "l"(p));
    return a;
}
__device__ __forceinline__ void cpa16(uint32_t s, const void* g) {
    asm volatile("cp.async.cg.shared.global [%0], [%1], 16;" :: "r"(s), "l"(g));
}
#define CP_COMMIT() asm volatile("cp.async.commit_group;" ::: "memory")
#define CP_WAIT0()  asm volatile("cp.async.wait_group 0;" ::: "memory")

#define LDSM_X4(r0, r1, r2, r3, a) \
    asm volatile("ldmatrix.sync.aligned.m8n8.x4.shared.b16 {%0,%1,%2,%3}, [%4];" \
                 : "=r"(r0), "=r"(r1), "=r"(r2), "=r"(r3) : "r"(a))

__device__ __forceinline__ void mma1688(float* c, const uint32_t* a,
                                        uint32_t b0, uint32_t b1) {
    asm volatile(
        "mma.sync.aligned.m16n8k8.row.col.f32.tf32.tf32.f32 "
        "{%0,%1,%2,%3}, {%4,%5,%6,%7}, {%8,%9}, {%0,%1,%2,%3};"
        : "+f"(c[0]), "+f"(c[1]), "+f"(c[2]), "+f"(c[3])
        : "r"(a[0]), "r"(a[1]), "r"(a[2]), "r"(a[3]), "r"(b0), "r"(b1));
}

// Exact register split: hi = trunc-to-tf32(a), lo = (a-hi) masked to tf32.
__device__ __forceinline__ void tsplit2(uint32_t r, uint32_t& h, uint32_t& l) {
    h = r & 0xFFFFE000u;
    float lf = __uint_as_float(r) - __uint_as_float(h);
    l = __float_as_uint(lf) & 0xFFFFE000u;
}

__device__ __forceinline__ float sigm(float x) {
    return 1.0f / (1.0f + __expf(-x));
}

// ---------------------------------------------------------------------------
// prep_Wt: g_Wt[(c*64+j)*32 + k] = W[(c*32+k)*64 + j]
// ---------------------------------------------------------------------------
__global__ __launch_bounds__(256)
void prep_Wt(const float* __restrict__ W) {
    int i = blockIdx.x * 256 + threadIdx.x;    // 0..28671
    if (i < 14 * 64 * 32) {
        int c = i >> 11;
        int rem = i & 2047;
        int j = rem >> 5;
        int k = rem & 31;
        g_Wt[i] = W[(c * 32 + k) * 64 + j];
    }
}

// ---------------------------------------------------------------------------
// conv_rhs: build Bt[j][k] = src[b][k][f] (j = src*128 + b*32 + f), raw fp32
// ---------------------------------------------------------------------------
__global__ __launch_bounds__(256)
void conv_rhs(const float* __restrict__ s0in, const float* __restrict__ s1,
              int s0_is_h1) {
    __shared__ float t[64][33];
    const int tid = threadIdx.x;
    const int src = blockIdx.y >> 2;
    const int b   = blockIdx.y & 3;
    const int k0  = blockIdx.x * 64;

    const float* s0 = s0_is_h1 ? (const float*)g_h1 : s0in;
    const float* sp = (src == 0) ? s0 : s1;
    const float* base = sp + b * NF + k0 * Ff;

    #pragma unroll
    for (int i = 0; i < 2; i++) {
        int fi = tid + 256 * i;
        int row = fi >> 3, quad = fi & 7;
        float4 v = *(const float4*)(base + row * Ff + quad * 4);
        t[row][quad * 4 + 0] = v.x; t[row][quad * 4 + 1] = v.y;
        t[row][quad * 4 + 2] = v.z; t[row][quad * 4 + 3] = v.w;
    }
    __syncthreads();

    const int j0 = src * 128 + b * Ff;
    #pragma unroll
    for (int i = 0; i < 2; i++) {
        int oi = tid + 256 * i;
        int f  = oi >> 4;
        int kq = oi & 15;
        float4 v = make_float4(t[kq * 4 + 0][f], t[kq * 4 + 1][f],
                               t[kq * 4 + 2][f], t[kq * 4 + 3][f]);
        *(float4*)(g_Bt + (long long)(j0 + f) * Nn + k0 + kq * 4) = v;
    }
}

// ---------------------------------------------------------------------------
// agg_mma: unchanged from R10 (passing). tf32 3-pass register-split GEMM.
// ---------------------------------------------------------------------------
#define AROWB 144
#define A_O   0
#define B_O   (128 * AROWB)
#define STG_B (2 * 128 * AROWB)
#define AGG_SMEM (2 * STG_B)

__global__ __launch_bounds__(256, 1)
void agg_mma(const float* __restrict__ Araw) {
    extern __shared__ __align__(16) char dsm[];
    const uint32_t sm0 = smem_u32(dsm);

    const int tid  = threadIdx.x;
    const int wid  = tid >> 5;
    const int lane = tid & 31;
    const int m0   = blockIdx.x * 128;
    const int n0   = blockIdx.y * 128;
    const int ksz  = blockIdx.z;
    const int kbase = ksz * 2048;

    const int wm = wid & 3;
    const int wn = wid >> 2;
    const int t  = lane & 3;
    const int g  = lane >> 2;

    const int a_off = (wm * 32 + (lane & 15)) * AROWB + (lane >> 4) * 16;
    const int b_off = (wn * 64 + (lane & 15)) * AROWB + (lane >> 4) * 16;

    float acc[2][8][4];
    #pragma unroll
    for (int mf = 0; mf < 2; mf++)
        #pragma unroll
        for (int nf = 0; nf < 8; nf++)
            #pragma unroll
            for (int q = 0; q < 4; q++) acc[mf][nf][q] = 0.0f;

    const int NKT = 2048 / 32;

    auto load_stage = [&](int st, int kc) {
        const uint32_t stg = sm0 + st * STG_B;
        const int k0 = kbase + kc * 32;
        #pragma unroll
        for (int i = 0; i < 4; i++) {
            int sid = tid + 256 * i;
            int r = sid >> 3, s = sid & 7;
            uint32_t soff = r * AROWB + s * 16;
            cpa16(stg + A_O + soff, Araw + (long long)(m0 + r) * Nn + k0 + s * 4);
            cpa16(stg + B_O + soff, g_Bt + (long long)(n0 + r) * Nn + k0 + s * 4);
        }
    };

    load_stage(0, 0); CP_COMMIT();
    load_stage(1, 1); CP_COMMIT();

    for (int kc = 0; kc < NKT; kc++) {
        if (kc == NKT - 1) {
            asm volatile("cp.async.wait_group 0;" ::: "memory");
        } else {
            asm volatile("cp.async.wait_group 1;" ::: "memory");
        }
        __syncthreads();

        const int st = kc & 1;
        const uint32_t stg = sm0 + st * STG_B;

        #pragma unroll
        for (int k8 = 0; k8 < 4; k8++) {
            const uint32_t ko = k8 * 32;

            uint32_t ar0[4], ar1[4];
            LDSM_X4(ar0[0], ar0[1], ar0[2], ar0[3], stg + A_O + a_off + ko);
            LDSM_X4(ar1[0], ar1[1], ar1[2], ar1[3],
                    stg + A_O + a_off + ko + 16 * AROWB);
            uint32_t ah[2][4], al[2][4];
            #pragma unroll
            for (int q = 0; q < 4; q++) {
                tsplit2(ar0[q], ah[0][q], al[0][q]);
                tsplit2(ar1[q], ah[1][q], al[1][q]);
            }

            #pragma unroll
            for (int nbi = 0; nbi < 4; nbi++) {
                uint32_t br[4];
                LDSM_X4(br[0], br[1], br[2], br[3],
                        stg + B_O + b_off + nbi * 16 * AROWB + ko);
                uint32_t bh[4], bl[4];
                #pragma unroll
                for (int q = 0; q < 4; q++) tsplit2(br[q], bh[q], bl[q]);

                const int nf0 = nbi * 2;
                mma1688(acc[0][nf0 + 0], ah[0], bh[0], bh[2]);
                mma1688(acc[0][nf0 + 1], ah[0], bh[1], bh[3]);
                mma1688(acc[1][nf0 + 0], ah[1], bh[0], bh[2]);
                mma1688(acc[1][nf0 + 1], ah[1], bh[1], bh[3]);
                mma1688(acc[0][nf0 + 0], al[0], bh[0], bh[2]);
                mma1688(acc[0][nf0 + 1], al[0], bh[1], bh[3]);
                mma1688(acc[1][nf0 + 0], al[1], bh[0], bh[2]);
                mma1688(acc[1][nf0 + 1], al[1], bh[1], bh[3]);
                mma1688(acc[0][nf0 + 0], ah[0], bl[0], bl[2]);
                mma1688(acc[0][nf0 + 1], ah[0], bl[1], bl[3]);
                mma1688(acc[1][nf0 + 0], ah[1], bl[0], bl[2]);
                mma1688(acc[1][nf0 + 1], ah[1], bl[1], bl[3]);
            }
        }
        __syncthreads();

        if (kc + 2 < NKT) { load_stage(st, kc + 2); CP_COMMIT(); }
    }

    float* outp = g_part + (long long)ksz * (Nn * CC);
    const int c2 = t * 2;
    #pragma unroll
    for (int mf = 0; mf < 2; mf++) {
        #pragma unroll
        for (int nf = 0; nf < 8; nf++) {
            const int row = m0 + wm * 32 + mf * 16 + g;
            const int col = n0 + wn * 64 + nf * 8 + c2;
            *(float2*)&outp[(long long)row * CC + col] =
                make_float2(acc[mf][nf][0], acc[mf][nf][1]);
            *(float2*)&outp[(long long)(row + 8) * CC + col] =
                make_float2(acc[mf][nf][2], acc[mf][nf][3]);
        }
    }
}

// ---------------------------------------------------------------------------
// reduce_agg: g_agg = part0 + part1
// ---------------------------------------------------------------------------
__global__ __launch_bounds__(256)
void reduce_agg() {
    const int i4 = blockIdx.x * 256 + threadIdx.x;
    const float4* P = (const float4*)g_part;
    const int S = (Nn * CC) / 4;
    float4 a = P[i4], b = P[S + i4];
    ((float4*)g_agg)[i4] = make_float4(a.x + b.x, a.y + b.y, a.z + b.z, a.w + b.w);
}

// ---------------------------------------------------------------------------
// gates via tensor cores.
// CTA: 64 rows (idx) x [NGATES x 128 cols]. Warps: 2m x 4n (wn = gate).
// Warp tile 32 rows x 128 cols = [zx(64) | zh(64)] of its gate.
// Z = A @ Wt-blocks, tf32 3-pass, K=32 per half. GLU + x/h-sum in registers;
// 4-gate combine via smem exchange; LSTM math fused in epilogue.
//
// smem: A 64x(64+4pad)=17408B, B 512x144B=73728B, bias 2048B, pre 32768B
// ---------------------------------------------------------------------------
#define GA_ROWB 272                       // 64 fp32 + 16B pad
#define GSM_A   0
#define GSM_B   (64 * GA_ROWB)            // 17408
#define GSM_BIAS (GSM_B + 512 * 144)      // 91136
#define GSM_PRE  (GSM_BIAS + 2048)        // 93184
#define GATES_SMEM (GSM_PRE + 4 * 64 * 32 * 4)   // 125952

template <int NGATES, int WOFF>
__device__ __forceinline__ void gates_core(char* dsm, int idx0, int tid,
                                           const float* bias,
                                           float pre_out[2][4][4],
                                           int& wm_o, int& wn_o) {
    const uint32_t sm0 = smem_u32(dsm);
    const int wid  = tid >> 5;
    const int lane = tid & 31;
    const int wm = wid & 1;          // 2 row-groups of 32
    const int wn = wid >> 1;         // gate
    const int t  = lane & 3;
    wm_o = wm; wn_o = wn;

    // ---- A fill: 64 rows x 16 segs of 16B ----
    #pragma unroll
    for (int i = 0; i < 4; i++) {
        int sid = tid + 256 * i;               // 0..1023
        int r = sid >> 4, seg = sid & 15;
        int idx = idx0 + r;
        int b = idx >> 12, n = idx & (Nn - 1);
        int goff = n * CC + ((seg < 8) ? (b * 32 + seg * 4)
                                       : (128 + b * 32 + (seg - 8) * 4));
        cpa16(sm0 + GSM_A + r * GA_ROWB + seg * 16, g_agg + goff);
    }
    // ---- B fill: NGATES*128 cols x 8 segs ----
    const int NB = NGATES * 128 * 8;
    for (int sid = tid; sid < NB; sid += 256) {
        int col = sid >> 3, seg = sid & 7;
        cpa16(sm0 + GSM_B + col * 144 + seg * 16,
              g_Wt + (WOFF + col) * 32 + seg * 4);
    }
    // ---- bias fill ----
    float* smBias = (float*)(dsm + GSM_BIAS);
    for (int colz = tid; colz < NGATES * 128; colz += 256)
        smBias[colz] = bias[WOFF + colz];
    CP_COMMIT(); CP_WAIT0();
    __syncthreads();

    float acc[2][16][4];
    #pragma unroll
    for (int mf = 0; mf < 2; mf++)
        #pragma unroll
        for (int nf = 0; nf < 16; nf++)
            #pragma unroll
            for (int q = 0; q < 4; q++) acc[mf][nf][q] = 0.0f;

    if (wn < NGATES) {
        const uint32_t a_base = sm0 + GSM_A +
            (wm * 32 + (lane & 15)) * GA_ROWB + (lane >> 4) * 16;
        const uint32_t b_base = sm0 + GSM_B +
            (wn * 128 + (lane & 15)) * 144 + (lane >> 4) * 16;

        #pragma unroll
        for (int k8 = 0; k8 < 4; k8++) {
            // A frags: x at +k8*32, h at +128+k8*32
            uint32_t arx0[4], arx1[4], arh0[4], arh1[4];
            LDSM_X4(arx0[0], arx0[1], arx0[2], arx0[3], a_base + k8 * 32);
            LDSM_X4(arx1[0], arx1[1], arx1[2], arx1[3],
                    a_base + k8 * 32 + 16 * GA_ROWB);
            LDSM_X4(arh0[0], arh0[1], arh0[2], arh0[3], a_base + 128 + k8 * 32);
            LDSM_X4(arh1[0], arh1[1], arh1[2], arh1[3],
                    a_base + 128 + k8 * 32 + 16 * GA_ROWB);
            uint32_t axh[2][4], axl[2][4], ahh[2][4], ahl[2][4];
            #pragma unroll
            for (int q = 0; q < 4; q++) {
                tsplit2(arx0[q], axh[0][q], axl[0][q]);
                tsplit2(arx1[q], axh[1][q], axl[1][q]);
                tsplit2(arh0[q], ahh[0][q], ahl[0][q]);
                tsplit2(arh1[q], ahh[1][q], ahl[1][q]);
            }

            #pragma unroll
            for (int nbi = 0; nbi < 8; nbi++) {
                uint32_t br[4];
                LDSM_X4(br[0], br[1], br[2], br[3],
                        b_base + nbi * 16 * 144 + k8 * 32);
                uint32_t bh[4], bl[4];
                #pragma unroll
                for (int q = 0; q < 4; q++) tsplit2(br[q], bh[q], bl[q]);

                const int nf0 = nbi * 2;
                uint32_t (*aH)[4] = (nbi < 4) ? axh : ahh;
                uint32_t (*aL)[4] = (nbi < 4) ? axl : ahl;
                mma1688(acc[0][nf0 + 0], aH[0], bh[0], bh[2]);
                mma1688(acc[0][nf0 + 1], aH[0], bh[1], bh[3]);
                mma1688(acc[1][nf0 + 0], aH[1], bh[0], bh[2]);
                mma1688(acc[1][nf0 + 1], aH[1], bh[1], bh[3]);
                mma1688(acc[0][nf0 + 0], aL[0], bh[0], bh[2]);
                mma1688(acc[0][nf0 + 1], aL[0], bh[1], bh[3]);
                mma1688(acc[1][nf0 + 0], aL[1], bh[0], bh[2]);
                mma1688(acc[1][nf0 + 1], aL[1], bh[1], bh[3]);
                mma1688(acc[0][nf0 + 0], aH[0], bl[0], bl[2]);
                mma1688(acc[0][nf0 + 1], aH[0], bl[1], bl[3]);
                mma1688(acc[1][nf0 + 0], aH[1], bl[0], bl[2]);
                mma1688(acc[1][nf0 + 1], aH[1], bl[1], bl[3]);
            }
        }

        // bias add
        float bv[16][2];
        #pragma unroll
        for (int nf = 0; nf < 16; nf++)
            #pragma unroll
            for (int p = 0; p < 2; p++)
                bv[nf][p] = smBias[wn * 128 + nf * 8 + t * 2 + p];
        #pragma unroll
        for (int mf = 0; mf < 2; mf++)
            #pragma unroll
            for (int nf = 0; nf < 16; nf++)
                #pragma unroll
                for (int q = 0; q < 4; q++)
                    acc[mf][nf][q] += bv[nf][q & 1];

        // GLU per conv + x/h sum: pre = zx_l*sigm(zx_r) + zh_l*sigm(zh_r)
        #pragma unroll
        for (int mf = 0; mf < 2; mf++)
            #pragma unroll
            for (int nf = 0; nf < 4; nf++)
                #pragma unroll
                for (int q = 0; q < 4; q++)
                    pre_out[mf][nf][q] =
                        acc[mf][nf][q]      * sigm(acc[mf][nf + 4][q]) +
                        acc[mf][nf + 8][q]  * sigm(acc[mf][nf + 12][q]);
    }
}

__global__ __launch_bounds__(256, 1)
void gates1_mma(const float* __restrict__ c_in,
                const float* __restrict__ bias,
                float* __restrict__ c_out)
{
    extern __shared__ __align__(16) char dsm[];
    const int tid  = threadIdx.x;
    const int lane = tid & 31;
    const int idx0 = blockIdx.x * 64;

    float pre[2][4][4];
    int wm, wn;
    gates_core<4, 0>(dsm, idx0, tid, bias, pre, wm, wn);

    // write pre to smem exchange
    float* smPre = (float*)(dsm + GSM_PRE);
    {
        const int t = lane & 3, g = lane >> 2;
        #pragma unroll
        for (int mf = 0; mf < 2; mf++)
            #pragma unroll
            for (int nf = 0; nf < 4; nf++)
                #pragma unroll
                for (int q = 0; q < 4; q++) {
                    int row = wm * 32 + mf * 16 + g + ((q >> 1) ? 8 : 0);
                    int j = nf * 8 + t * 2 + (q & 1);
                    smPre[wn * 2048 + row * 32 + j] = pre[mf][nf][q];
                }
    }
    __syncthreads();

    // final LSTM math: gates 0..3 = f, i, cand, o
    #pragma unroll
    for (int u = 0; u < 8; u++) {
        int cell = tid + 256 * u;     // row*32 + j
        float pf = smPre[cell];
        float pi = smPre[2048 + cell];
        float pc = smPre[2 * 2048 + cell];
        float po = smPre[3 * 2048 + cell];
        float cn = sigm(pf) * c_in[(long long)idx0 * 32 + cell] +
                   sigm(pi) * tanhf(pc);
        c_out[(long long)idx0 * 32 + cell] = cn;
        g_h1[(long long)idx0 * 32 + cell] = sigm(po) * tanhf(cn);
    }
}

__global__ __launch_bounds__(256, 1)
void gates2_mma(const float* __restrict__ m_in,
                const float* __restrict__ bias,
                float* __restrict__ h_out,
                float* __restrict__ m_out)
{
    extern __shared__ __align__(16) char dsm[];
    const int tid  = threadIdx.x;
    const int lane = tid & 31;
    const int idx0 = blockIdx.x * 64;

    float pre[2][4][4];
    int wm, wn;
    gates_core<3, 512>(dsm, idx0, tid, bias + 0, pre, wm, wn);
    // note: WOFF=512 -> g_Wt rows for convs 8..13; bias offset handled below

    float* smPre = (float*)(dsm + GSM_PRE);
    if (wn < 3) {
        const int t = lane & 3, g = lane >> 2;
        #pragma unroll
        for (int mf = 0; mf < 2; mf++)
            #pragma unroll
            for (int nf = 0; nf < 4; nf++)
                #pragma unroll
                for (int q = 0; q < 4; q++) {
                    int row = wm * 32 + mf * 16 + g + ((q >> 1) ? 8 : 0);
                    int j = nf * 8 + t * 2 + (q & 1);
                    smPre[wn * 2048 + row * 32 + j] = pre[mf][nf][q];
                }
    }
    __syncthreads();

    // gates 0..2 = i2, g, o2
    #pragma unroll
    for (int u = 0; u < 8; u++) {
        int cell = tid + 256 * u;
        float i2 = sigm(smPre[cell]);
        float gg = sigm(smPre[2048 + cell]);
        float o2 = sigm(smPre[2 * 2048 + cell]);
        float mn = i2 * m_in[(long long)idx0 * 32 + cell] + (1.0f - i2) * gg;
        m_out[(long long)idx0 * 32 + cell] = mn;
        h_out[(long long)idx0 * 32 + cell] = mn * o2;
    }
}

// ---------------------------------------------------------------------------
// Launch
// ---------------------------------------------------------------------------
extern "C" void kernel_launch(void* const* d_in, const int* in_sizes, int n_in,
                              void* d_out, int out_size) {
    const float* x    = (const float*)d_in[0];
    const float* h    = (const float*)d_in[1];
    const float* c    = (const float*)d_in[2];
    const float* m    = (const float*)d_in[3];
    const float* adj  = (const float*)d_in[4];
    const float* W    = (const float*)d_in[5];
    const float* bias = (const float*)d_in[6];

    float* out   = (float*)d_out;
    float* h_out = out;               // h_new
    float* c_out = out + BNF;         // c_new
    float* m_out = out + 2 * BNF;     // m_new

    cudaFuncSetAttribute(agg_mma, cudaFuncAttributeMaxDynamicSharedMemorySize, AGG_SMEM);
    cudaFuncSetAttribute(gates1_mma, cudaFuncAttributeMaxDynamicSharedMemorySize, GATES_SMEM);
    cudaFuncSetAttribute(gates2_mma, cudaFuncAttributeMaxDynamicSharedMemorySize, GATES_SMEM);

    prep_Wt<<<112, 256>>>(W);

    dim3 agrid(32, 2, 2);

    // Phase 1
    conv_rhs<<<dim3(64, 8), 256>>>(x, h, 0);
    agg_mma<<<agrid, 256, AGG_SMEM>>>(adj);
    reduce_agg<<<1024, 256>>>();
    gates1_mma<<<256, 256, GATES_SMEM>>>(c, bias, c_out);

    // Phase 2
    conv_rhs<<<dim3(64, 8), 256>>>(nullptr, m, 1);
    agg_mma<<<agrid, 256, AGG_SMEM>>>(adj);
    reduce_agg<<<1024, 256>>>();
    gates2_mma<<<256, 256, GATES_SMEM>>>(m, bias, h_out, m_out);
}